// round 16
// baseline (speedup 1.0000x reference)
#include <cuda_runtime.h>
#include <cstdint>

// Problem constants (B=4, L=4096, C=1024, K=4096)
#define NPTS 16384
#define CDIM 1024
#define KCB  4096

// Device scratch (no allocations allowed)
__device__ float              g_feat[NPTS * CDIM];   // normalized points (64 MB)
__device__ float              g_cbn2[KCB];           // ||cb_k||^2
__device__ float              g_sums[KCB * CDIM];    // per-cluster sums (16 MB)
__device__ int                g_cnt[KCB];            // per-cluster counts
__device__ unsigned long long g_best[NPTS];          // packed (orderable_f32 << 32) | idx

// Packed fp32x2 FMA (sm_103a FFMA2; two independent IEEE fp32 FMAs)
#define FFMA2(d, a, b, c) \
    asm("fma.rn.f32x2 %0, %1, %2, %3;" : "=l"(d) : "l"(a), "l"(b), "l"(c))

// ---------------------------------------------------------------------------
// Init: zero accumulators, set best to +inf (graph-replay safe)
// ---------------------------------------------------------------------------
__global__ void init_kernel() {
    int i = blockIdx.x * blockDim.x + threadIdx.x;
    int stride = gridDim.x * blockDim.x;
    for (int j = i; j < KCB * CDIM; j += stride) g_sums[j] = 0.f;
    for (int j = i; j < KCB; j += stride) g_cnt[j] = 0;
    for (int j = i; j < NPTS; j += stride) g_best[j] = 0xFFFFFFFFFFFFFFFFull;
}

// ---------------------------------------------------------------------------
// Row-normalize hidden_states -> g_feat   (one 256-thread block per row)
// ---------------------------------------------------------------------------
__global__ void norm_feat_kernel(const float* __restrict__ hs) {
    int row = blockIdx.x;
    int t = threadIdx.x;
    float v[4];
    float ss = 0.f;
#pragma unroll
    for (int j = 0; j < 4; j++) {
        v[j] = hs[(size_t)row * CDIM + t + j * 256];
        ss += v[j] * v[j];
    }
    __shared__ float red[256];
    red[t] = ss;
    __syncthreads();
    for (int s = 128; s > 0; s >>= 1) {
        if (t < s) red[t] += red[t + s];
        __syncthreads();
    }
    float inv = 1.f / fmaxf(sqrtf(red[0]), 1e-6f);
#pragma unroll
    for (int j = 0; j < 4; j++)
        g_feat[(size_t)row * CDIM + t + j * 256] = v[j] * inv;
}

// ---------------------------------------------------------------------------
// ||cb_k||^2  (one block per code)
// ---------------------------------------------------------------------------
__global__ void cbn2_kernel(const float* __restrict__ cb) {
    int row = blockIdx.x;
    int t = threadIdx.x;
    float ss = 0.f;
#pragma unroll
    for (int j = 0; j < 4; j++) {
        float x = cb[(size_t)row * CDIM + t + j * 256];
        ss += x * x;
    }
    __shared__ float red[256];
    red[t] = ss;
    __syncthreads();
    for (int s = 128; s > 0; s >>= 1) {
        if (t < s) red[t] += red[t + s];
        __syncthreads();
    }
    if (t == 0) g_cbn2[row] = red[0];
}

// ---------------------------------------------------------------------------
// Fused GEMM + argmin: 2 CTAs/SM for latency hiding.
//
// R9 ncu: fma=61%, issue=42%, occ=12.5% (2 warps/SMSP) -> latency-bound, not
// fma-bound. Fix: halve per-thread tile so regs fit 128 and TWO 256-thread
// CTAs co-reside per SM (16 warps, 4/SMSP). One CTA's load/barrier phases are
// covered by the other CTA's compute, so the register prefetch pipeline is
// dropped (frees 24 regs).
//
// Block tile 256 rows x 64 codes; C-chunks of 16. Thread tile: 16 rows
// (8 packed pairs, pair = tx + 16p) x 4 codes (k = ty + 16s, s<4),
// tx = t&15, ty = t>>4.
//  - As[c][256] transposed rows (stride 258): a-read = LDS.64, 16 lanes x 8B
//    contiguous + upper-half broadcast -> 1 wf; stores hit banks {0,8,16,24}.
//  - Bs[c][128] duplicated codes (stride 130): b-read = half-warp broadcast.
//  - Per cc-step/SM (16 warps): fma 256 cyc vs crossbar ~192 -> fma-bound.
//  - Chunk loop pinned "#pragma unroll 1" (I$: body fits L1.5).
//  - __launch_bounds__(256, 2): ptxas must fit 128 regs -> 2 CTAs/SM.
//    smem 24.8 KB/CTA -> 49.7 KB for both, far under the 228 KB carveout.
//  - Grid (64, 64) = 4096 blocks; 296 concurrent -> 13.84 waves, 98.8% util.
// Merges via atomicMin on packed (orderable_key<<32)|idx so ties pick the
// smallest index (jnp.argmin semantics).
// ---------------------------------------------------------------------------
#define BM 256
#define BKC 64                   // codes per tile (= per block)
#define BC 16                    // c-chunk
#define ASTRIDE 258              // As row stride (floats)
#define BSTRIDE 130              // Bs row stride (floats)
#define NCHUNK (CDIM / BC)       // 64

__global__ __launch_bounds__(256, 2) void argmin_kernel(const float* __restrict__ cb) {
    __shared__ __align__(16) float As[BC][ASTRIDE];
    __shared__ __align__(16) float Bs[BC][BSTRIDE];

    int t = threadIdx.x;
    int tx = t & 15;
    int ty = t >> 4;             // 0..15
    int rowBase = blockIdx.x * BM;
    int kBase = blockIdx.y * BKC;

    // Load coordinates: A 4 float4/thread (256x16), B 1 float4/thread (64x16)
    int raBase = t >> 2;         // 0..63 (A row, +64 per i)
    int caOff = (t & 3) * 4;     // 0,4,8,12
    int rbB = t >> 2;            // 0..63 (B code)

    unsigned long long acc[8][4];  // [row-pair p][code s], packed f32x2
#pragma unroll
    for (int p = 0; p < 8; p++)
#pragma unroll
        for (int s = 0; s < 4; s++) acc[p][s] = 0ull;

#pragma unroll 1
    for (int ch = 0; ch < NCHUNK; ++ch) {
        int c0 = ch * BC;
        __syncthreads();  // previous compute done reading smem
        // A: 256 rows x 16 c -> As[c][row] (transposed)
#pragma unroll
        for (int i = 0; i < 4; i++) {
            int r = raBase + i * 64;
            float4 f = *(const float4*)&g_feat[(size_t)(rowBase + r) * CDIM + c0 + caOff];
            As[caOff + 0][r] = f.x; As[caOff + 1][r] = f.y;
            As[caOff + 2][r] = f.z; As[caOff + 3][r] = f.w;
        }
        // B: 64 codes x 16 c -> Bs[c][2k],[2k+1] duplicated
        {
            float4 g = *(const float4*)&cb[(size_t)(kBase + rbB) * CDIM + c0 + caOff];
            *(float2*)&Bs[caOff + 0][2 * rbB] = make_float2(g.x, g.x);
            *(float2*)&Bs[caOff + 1][2 * rbB] = make_float2(g.y, g.y);
            *(float2*)&Bs[caOff + 2][2 * rbB] = make_float2(g.z, g.z);
            *(float2*)&Bs[caOff + 3][2 * rbB] = make_float2(g.w, g.w);
        }
        __syncthreads();

#pragma unroll
        for (int cc = 0; cc < BC; ++cc) {
            unsigned long long a[8], b[4];
#pragma unroll
            for (int p = 0; p < 8; p++)
                a[p] = *(const unsigned long long*)&As[cc][2 * (tx + 16 * p)];
#pragma unroll
            for (int s = 0; s < 4; s++)
                b[s] = *(const unsigned long long*)&Bs[cc][2 * (ty + 16 * s)];
#pragma unroll
            for (int p = 0; p < 8; p++)
#pragma unroll
                for (int s = 0; s < 4; s++)
                    FFMA2(acc[p][s], a[p], b[s], acc[p][s]);
        }
    }

    // Epilogue (best arrays born after acc's last use)
    float bestv[16];
    int besti[16];
#pragma unroll
    for (int i = 0; i < 16; i++) { bestv[i] = 3.4e38f; besti[i] = 0x7fffffff; }

    // score = ||cb||^2 - 2*dot ; strict < keeps smallest index (k ascends
    // with s for each thread).
#pragma unroll
    for (int s = 0; s < 4; s++) {
        int k = kBase + ty + 16 * s;
        float c2 = g_cbn2[k];
#pragma unroll
        for (int p = 0; p < 8; p++) {
            float dlo = __uint_as_float((unsigned)(acc[p][s] & 0xFFFFFFFFull));
            float dhi = __uint_as_float((unsigned)(acc[p][s] >> 32));
            float slo = fmaf(-2.f, dlo, c2);
            float shi = fmaf(-2.f, dhi, c2);
            if (slo < bestv[2 * p])     { bestv[2 * p] = slo;     besti[2 * p] = k; }
            if (shi < bestv[2 * p + 1]) { bestv[2 * p + 1] = shi; besti[2 * p + 1] = k; }
        }
    }

    // Lanes l and l^16 hold the same rows (same tx; ty differs by 1) ->
    // intra-warp merge over their two code subsets, then the lower half-warp
    // commits with atomicMin (cross-warp/cross-block merge).
#pragma unroll
    for (int i = 0; i < 16; i++) {
        float v = bestv[i];
        int idx = besti[i];
        float ov = __shfl_xor_sync(0xFFFFFFFFu, v, 16);
        int oi = __shfl_xor_sync(0xFFFFFFFFu, idx, 16);
        if (ov < v || (ov == v && oi < idx)) { v = ov; idx = oi; }
        if ((t & 16) == 0) {
            int p = i >> 1;
            int row = rowBase + 2 * (tx + 16 * p) + (i & 1);
            unsigned key = __float_as_uint(v);
            key = (key & 0x80000000u) ? ~key : (key | 0x80000000u);
            unsigned long long packed =
                ((unsigned long long)key << 32) | (unsigned)idx;
            atomicMin(&g_best[row], packed);
        }
    }
}

// ---------------------------------------------------------------------------
// Decode ids, write them out, and scatter-add feat rows into cluster sums.
// ---------------------------------------------------------------------------
__global__ void scatter_kernel(float* __restrict__ out_ids) {
    int row = blockIdx.x;
    __shared__ int sidx;
    if (threadIdx.x == 0) {
        int idx = (int)(g_best[row] & 0xFFFFFFFFull);
        sidx = idx;
        out_ids[row] = (float)idx;
        atomicAdd(&g_cnt[idx], 1);
    }
    __syncthreads();
    int idx = sidx;
    const float* f = &g_feat[(size_t)row * CDIM];
    float* s = &g_sums[(size_t)idx * CDIM];
#pragma unroll
    for (int j = 0; j < 4; j++) {
        int c = threadIdx.x + j * 256;
        atomicAdd(&s[c], f[c]);
    }
}

// ---------------------------------------------------------------------------
// EMA update: mean = normalize(sums / max(cnt,1));
// new = normalize(0.99*cb + 0.01*mean); keep old code if cnt == 0.
// ---------------------------------------------------------------------------
__global__ void update_kernel(const float* __restrict__ cb, float* __restrict__ out_cb) {
    int k = blockIdx.x;
    int t = threadIdx.x;
    int cnt = g_cnt[k];
    float denom = fmaxf((float)cnt, 1.f);

    float m[4], c[4];
    float ss = 0.f;
#pragma unroll
    for (int j = 0; j < 4; j++) {
        int col = t + j * 256;
        m[j] = g_sums[(size_t)k * CDIM + col] / denom;
        c[j] = cb[(size_t)k * CDIM + col];
        ss += m[j] * m[j];
    }
    __shared__ float red[256];
    red[t] = ss;
    __syncthreads();
    for (int s = 128; s > 0; s >>= 1) {
        if (t < s) red[t] += red[t + s];
        __syncthreads();
    }
    float inv1 = 1.f / fmaxf(sqrtf(red[0]), 1e-6f);

    float v[4];
    float ss2 = 0.f;
#pragma unroll
    for (int j = 0; j < 4; j++) {
        v[j] = 0.99f * c[j] + 0.01f * (m[j] * inv1);
        ss2 += v[j] * v[j];
    }
    __syncthreads();
    red[t] = ss2;
    __syncthreads();
    for (int s = 128; s > 0; s >>= 1) {
        if (t < s) red[t] += red[t + s];
        __syncthreads();
    }
    float inv2 = 1.f / fmaxf(sqrtf(red[0]), 1e-6f);

#pragma unroll
    for (int j = 0; j < 4; j++) {
        int col = t + j * 256;
        out_cb[(size_t)k * CDIM + col] = (cnt > 0) ? v[j] * inv2 : c[j];
    }
}

// ---------------------------------------------------------------------------
// Launch. Inputs: d_in[0] = hidden_states (B*L*C f32), d_in[1] = codebook (K*C f32).
// Output layout: [0, NPTS) cluster ids (as f32), [NPTS, NPTS + K*C) new codebook.
// ---------------------------------------------------------------------------
extern "C" void kernel_launch(void* const* d_in, const int* in_sizes, int n_in,
                              void* d_out, int out_size) {
    const float* hs = (const float*)d_in[0];
    const float* cb = (const float*)d_in[1];
    float* out = (float*)d_out;

    init_kernel<<<512, 256>>>();
    norm_feat_kernel<<<NPTS, 256>>>(hs);
    cbn2_kernel<<<KCB, 256>>>(cb);

    dim3 grid(NPTS / BM, KCB / BKC);  // (64, 64) = 4096 blocks
    argmin_kernel<<<grid, 256>>>(cb);

    scatter_kernel<<<NPTS, 256>>>(out);
    update_kernel<<<KCB, 256>>>(cb, out + NPTS);
}